// round 12
// baseline (speedup 1.0000x reference)
#include <cuda_runtime.h>
#include <cuda.h>
#include <cuda_fp16.h>
#include <cstdint>
#include <math.h>

#define L_LAYERS 4
#define BATCH    8
#define PHN      24
#define PWN      24
#define PATCHES  576
#define DIM      1024
#define NRL      12
#define NPAIRS   28
#define OUTH     336
#define OUTW     336
#define PADP     640
#define TILEM    288            // 576 = 2 x 288, zero padding
#define KS       64             // k per slab (128 B fp16, SW128)
#define NSLAB    16
#define NTHR     288            // 9 warps, 3x3 grid of 96x96 warp tiles
#define MATB     (TILEM * 128)  // 36864
#define STAGEB   (2 * MATB)     // 73728
#define TXB      STAGEB
#define SMEM_DYN (2048 + 2 * STAGEB)   // 149504 -> 1 CTA/SM

// ---------------- device scratch ----------------
__device__ __align__(128) __half g_featn[(size_t)NRL * BATCH * PADP * DIM];
__device__ unsigned g_keys[NRL * BATCH * PADP * BATCH];
__device__ float    g_scores[BATCH * PATCHES];
__device__ unsigned g_img[BATCH];

__device__ __forceinline__ unsigned enc_f(float x) {
    unsigned u = __float_as_uint(x);
    return (u & 0x80000000u) ? ~u : (u | 0x80000000u);
}
__device__ __forceinline__ float dec_f(unsigned k) {
    unsigned u = (k & 0x80000000u) ? (k & 0x7FFFFFFFu) : ~k;
    return __uint_as_float(u);
}
__device__ __forceinline__ uint32_t smem_u32(const void* p) {
    uint32_t a;
    asm("{ .reg .u64 t; cvta.to.shared.u64 t, %1; cvt.u32.u64 %0, t; }" : "=r"(a) : "l"(p));
    return a;
}

#define MBAR_INIT(a, n) asm volatile("mbarrier.init.shared.b64 [%0], %1;" :: "r"(a), "r"(n) : "memory")
#define MBAR_EXPECT(a, tx) asm volatile("mbarrier.arrive.expect_tx.shared.b64 _, [%0], %1;" :: "r"(a), "r"(tx) : "memory")
#define MBAR_WAIT(a, ph) do { \
    uint32_t _m = (a), _p = (ph), _d; \
    asm volatile("{ .reg .pred p; mbarrier.try_wait.parity.acquire.cta.shared::cta.b64 p, [%1], %2; selp.b32 %0,1,0,p; }" \
        : "=r"(_d) : "r"(_m), "r"(_p) : "memory"); \
    if (!_d) { asm volatile("{ .reg .pred P1; WL_%=: mbarrier.try_wait.parity.acquire.cta.shared::cta.b64 P1, [%0], %1, 0x989680; @P1 bra.uni WD_%=; bra.uni WL_%=; WD_%=: }" \
        :: "r"(_m), "r"(_p) : "memory"); } \
} while (0)

#define TMA_LOAD_2D(dst, map, cx, cy, mbar) \
    asm volatile("cp.async.bulk.tensor.2d.shared::cta.global.tile.mbarrier::complete_tx::bytes " \
        "[%0], [%1, {%2, %3}], [%4];" \
        :: "r"(dst), "l"(map), "r"(cx), "r"(cy), "r"(mbar) : "memory")

#define LDSM_X4(r0, r1, r2, r3, a) \
    asm volatile("ldmatrix.sync.aligned.m8n8.x4.shared.b16 {%0,%1,%2,%3}, [%4];" \
        : "=r"(r0), "=r"(r1), "=r"(r2), "=r"(r3) : "r"(a))

#define MMA16816H(c, a, b) \
    asm volatile("mma.sync.aligned.m16n8k16.row.col.f16.f16.f16.f16 " \
        "{%0,%1}, {%2,%3,%4,%5}, {%6,%7}, {%0,%1};" \
        : "+r"((c)[0]), "+r"((c)[1]) \
        : "r"((a)[0]), "r"((a)[1]), "r"((a)[2]), "r"((a)[3]), "r"((b)[0]), "r"((b)[1]))

// ---------------- pool + normalize -> fp16, also clears g_keys / g_img ------
__global__ void pool_norm_kernel(const float* __restrict__ feat) {
    int p = blockIdx.x, b = blockIdx.y, l = blockIdx.z;
    int ph = p / PWN, pw = p % PWN;
    int t = threadIdx.x;
    int d0 = t * 4;

    // fold init: clear g_keys (491520 uints over first 1920 blocks) + g_img
    {
        int lin = (l * BATCH + b) * PATCHES + p;
        if (lin < (NRL * BATCH * PADP * BATCH) / 256)
            g_keys[lin * 256 + t] = 0u;
        if (lin == 0 && t < BATCH) g_img[t] = 0u;
    }

    const float* base = feat + ((size_t)(l * BATCH + b) * PATCHES) * DIM;

    float4 s5 = make_float4(0.f, 0.f, 0.f, 0.f);
    float4 s3 = make_float4(0.f, 0.f, 0.f, 0.f);
    float4 s1 = make_float4(0.f, 0.f, 0.f, 0.f);

    #pragma unroll
    for (int dy = -2; dy <= 2; ++dy) {
        int y = ph + dy;
        if ((unsigned)y >= (unsigned)PHN) continue;
        #pragma unroll
        for (int dx = -2; dx <= 2; ++dx) {
            int x = pw + dx;
            if ((unsigned)x >= (unsigned)PWN) continue;
            const float4 v = *(const float4*)(base + (size_t)(y * PWN + x) * DIM + d0);
            s5.x += v.x; s5.y += v.y; s5.z += v.z; s5.w += v.w;
            if (dy >= -1 && dy <= 1 && dx >= -1 && dx <= 1) {
                s3.x += v.x; s3.y += v.y; s3.z += v.z; s3.w += v.w;
                if (dy == 0 && dx == 0) s1 = v;
            }
        }
    }
    s3.x *= (1.f/9.f);  s3.y *= (1.f/9.f);  s3.z *= (1.f/9.f);  s3.w *= (1.f/9.f);
    s5.x *= (1.f/25.f); s5.y *= (1.f/25.f); s5.z *= (1.f/25.f); s5.w *= (1.f/25.f);

    float q1 = s1.x*s1.x + s1.y*s1.y + s1.z*s1.z + s1.w*s1.w;
    float q3 = s3.x*s3.x + s3.y*s3.y + s3.z*s3.z + s3.w*s3.w;
    float q5 = s5.x*s5.x + s5.y*s5.y + s5.z*s5.z + s5.w*s5.w;
    #pragma unroll
    for (int o = 16; o > 0; o >>= 1) {
        q1 += __shfl_xor_sync(0xffffffffu, q1, o);
        q3 += __shfl_xor_sync(0xffffffffu, q3, o);
        q5 += __shfl_xor_sync(0xffffffffu, q5, o);
    }
    __shared__ float ws[3][8];
    __shared__ float rn[3];
    if ((t & 31) == 0) { ws[0][t >> 5] = q1; ws[1][t >> 5] = q3; ws[2][t >> 5] = q5; }
    __syncthreads();
    if (t < 3) {
        float x = 0.f;
        #pragma unroll
        for (int w = 0; w < 8; ++w) x += ws[t][w];
        rn[t] = rsqrtf(x);
    }
    __syncthreads();

    float4 vv[3] = { s1, s3, s5 };
    #pragma unroll
    for (int ri = 0; ri < 3; ++ri) {
        float r = rn[ri];
        __half2 lo = __floats2half2_rn(vv[ri].x * r, vv[ri].y * r);
        __half2 hi = __floats2half2_rn(vv[ri].z * r, vv[ri].w * r);
        uint2 pk = make_uint2(*(unsigned*)&lo, *(unsigned*)&hi);
        int z = ri * 4 + l;
        *(uint2*)(g_featn + ((size_t)(z * BATCH + b) * PADP + p) * DIM + d0) = pk;
    }
}

// ---------------- TMA + fp16 mma fused GEMM + bidirectional max --------------
// CTA tile 288x288, 9 warps (3x3) of 96x96, K slabs of 64 (SW128), 2-stage, 1 CTA/SM.
__global__ void __launch_bounds__(NTHR, 1) gemm_max_mma(const __grid_constant__ CUtensorMap tmap) {
    extern __shared__ __align__(16) char dsm[];
    uint32_t sraw = smem_u32(dsm);
    uint32_t ub   = (sraw + 1023) & ~1023u;
    uint32_t sstg = ub + 1024;

    int t = threadIdx.x;
    int wid = t >> 5, lane = t & 31;
    int warp_m = wid / 3;               // 0..2 rows of 96
    int warp_n = wid % 3;               // 0..2 cols of 96

    int tile = blockIdx.x;
    int ti = tile >> 1, tj = tile & 1;
    int pair = blockIdx.y, rl = blockIdx.z;

    int b = 0, rem = pair;
    #pragma unroll
    for (int bb = 0; bb < 7; ++bb) {
        int cnt = 7 - bb;
        if (rem < cnt) { b = bb; break; }
        rem -= cnt;
    }
    int c = b + 1 + rem;

    int rowA = (rl * BATCH + b) * PADP + ti * TILEM;
    int rowB = (rl * BATCH + c) * PADP + tj * TILEM;

    if (t == 0) {
        MBAR_INIT(ub, 1); MBAR_INIT(ub + 8, 1);
        asm volatile("fence.proxy.async.shared::cta;" ::: "memory");
    }
    __syncthreads();
    if (t == 0) {
        #pragma unroll
        for (int s = 0; s < 2; ++s) {
            MBAR_EXPECT(ub + s * 8, TXB);
            // 288 rows > TMA box limit 256 -> two 144-row loads per matrix
            TMA_LOAD_2D(sstg + s * STAGEB,               &tmap, s * 128, rowA,       ub + s * 8);
            TMA_LOAD_2D(sstg + s * STAGEB + 144 * 128,   &tmap, s * 128, rowA + 144, ub + s * 8);
            TMA_LOAD_2D(sstg + s * STAGEB + MATB,        &tmap, s * 128, rowB,       ub + s * 8);
            TMA_LOAD_2D(sstg + s * STAGEB + MATB + 144 * 128, &tmap, s * 128, rowB + 144, ub + s * 8);
        }
    }

    uint32_t acc[6][12][2];
    #pragma unroll
    for (int mi = 0; mi < 6; ++mi)
        #pragma unroll
        for (int ni = 0; ni < 12; ++ni) { acc[mi][ni][0] = 0u; acc[mi][ni][1] = 0u; }

    // SW128 swizzle in 128B-wide box: byte col c at row r -> c ^ ((r&7)<<4)
    int rA = warp_m * 96 + (lane & 15);
    uint32_t xorA = (uint32_t)((rA & 7) << 4);
    uint32_t abase = (uint32_t)(rA * 128);
    uint32_t koA[4];
    #pragma unroll
    for (int ks = 0; ks < 4; ++ks)
        koA[ks] = (uint32_t)((ks * 32 + (lane >> 4) * 16)) ^ xorA;

    int rB = warp_n * 96 + (lane >> 4) * 8 + (lane & 7);
    uint32_t xorB = (uint32_t)((rB & 7) << 4);
    uint32_t bbase = (uint32_t)(MATB + rB * 128);
    uint32_t koB[4];
    #pragma unroll
    for (int ks = 0; ks < 4; ++ks)
        koB[ks] = (uint32_t)((ks * 32 + ((lane >> 3) & 1) * 16)) ^ xorB;

    for (int kc = 0; kc < NSLAB; ++kc) {
        int st = kc & 1;
        MBAR_WAIT(ub + st * 8, (kc >> 1) & 1);

        uint32_t Sb = sstg + st * STAGEB;

        #pragma unroll
        for (int ks = 0; ks < 4; ++ks) {
            uint32_t afr[6][4];
            #pragma unroll
            for (int mi = 0; mi < 6; ++mi)
                LDSM_X4(afr[mi][0], afr[mi][1], afr[mi][2], afr[mi][3],
                        Sb + abase + mi * 2048 + koA[ks]);
            uint32_t bfr[12][2];
            #pragma unroll
            for (int np = 0; np < 6; ++np)
                LDSM_X4(bfr[np * 2][0], bfr[np * 2][1], bfr[np * 2 + 1][0], bfr[np * 2 + 1][1],
                        Sb + bbase + np * 2048 + koB[ks]);
            #pragma unroll
            for (int mi = 0; mi < 6; ++mi)
                #pragma unroll
                for (int ni = 0; ni < 12; ++ni)
                    MMA16816H(acc[mi][ni], afr[mi], bfr[ni]);
        }

        __syncthreads();   // all warps finished reading stage st
        if (t == 0 && kc + 2 < NSLAB) {
            MBAR_EXPECT(ub + st * 8, TXB);
            int cx = (kc + 2) * 128;
            TMA_LOAD_2D(Sb,               &tmap, cx, rowA,       ub + st * 8);
            TMA_LOAD_2D(Sb + 144 * 128,   &tmap, cx, rowA + 144, ub + st * 8);
            TMA_LOAD_2D(Sb + MATB,        &tmap, cx, rowB,       ub + st * 8);
            TMA_LOAD_2D(Sb + MATB + 144 * 128, &tmap, cx, rowB + 144, ub + st * 8);
        }
    }

    // ---------------- epilogue: bidirectional max ----------------
    // last slab read stage 1; stage-0 region (sstg) free.
    float* rowsmem = (float*)(dsm + (sstg - sraw));          // [3][288] by warp_n
    float* colsmem = rowsmem + 3 * TILEM;                    // [3][288] by warp_m

    #pragma unroll
    for (int mi = 0; mi < 6; ++mi) {
        __half2 h0 = __float2half2_rn(-60000.f), h1 = h0;
        #pragma unroll
        for (int ni = 0; ni < 12; ++ni) {
            h0 = __hmax2(h0, *(__half2*)&acc[mi][ni][0]);
            h1 = __hmax2(h1, *(__half2*)&acc[mi][ni][1]);
        }
        float rm0 = fmaxf(__low2float(h0), __high2float(h0));
        float rm1 = fmaxf(__low2float(h1), __high2float(h1));
        #pragma unroll
        for (int o = 1; o < 4; o <<= 1) {
            rm0 = fmaxf(rm0, __shfl_xor_sync(0xffffffffu, rm0, o));
            rm1 = fmaxf(rm1, __shfl_xor_sync(0xffffffffu, rm1, o));
        }
        if ((lane & 3) == 0) {
            int lr = warp_m * 96 + mi * 16 + (lane >> 2);
            rowsmem[warp_n * TILEM + lr]     = rm0;
            rowsmem[warp_n * TILEM + lr + 8] = rm1;
        }
    }

    #pragma unroll
    for (int ni = 0; ni < 12; ++ni) {
        __half2 hm = __float2half2_rn(-60000.f);
        #pragma unroll
        for (int mi = 0; mi < 6; ++mi) {
            hm = __hmax2(hm, *(__half2*)&acc[mi][ni][0]);
            hm = __hmax2(hm, *(__half2*)&acc[mi][ni][1]);
        }
        float cm0 = __low2float(hm);
        float cm1 = __high2float(hm);
        #pragma unroll
        for (int o = 4; o < 32; o <<= 1) {
            cm0 = fmaxf(cm0, __shfl_xor_sync(0xffffffffu, cm0, o));
            cm1 = fmaxf(cm1, __shfl_xor_sync(0xffffffffu, cm1, o));
        }
        if (lane < 4) {
            int lc = warp_n * 96 + ni * 8 + lane * 2;
            colsmem[warp_m * TILEM + lc]     = cm0;
            colsmem[warp_m * TILEM + lc + 1] = cm1;
        }
    }
    __syncthreads();

    {
        int idx = t;  // 0..287
        float mr = fmaxf(fmaxf(rowsmem[idx], rowsmem[TILEM + idx]), rowsmem[2 * TILEM + idx]);
        int p = ti * TILEM + idx;
        atomicMax(&g_keys[((size_t)(rl * BATCH + b) * PADP + p) * BATCH + c], enc_f(mr));
        float mc = fmaxf(fmaxf(colsmem[idx], colsmem[TILEM + idx]), colsmem[2 * TILEM + idx]);
        int q = tj * TILEM + idx;
        atomicMax(&g_keys[((size_t)(rl * BATCH + c) * PADP + q) * BATCH + b], enc_f(mc));
    }
}

// ---------------- score (+ fused image max) / bilinear ----------------
__global__ void score_kernel() {
    int idx = blockIdx.x * 128 + threadIdx.x;
    if (idx >= BATCH * PATCHES) return;
    int b = idx / PATCHES;
    int p = idx % PATCHES;

    float sum = 0.f;
    #pragma unroll
    for (int rl = 0; rl < NRL; ++rl) {
        const uint4* k4 = (const uint4*)&g_keys[((size_t)(rl * BATCH + b) * PADP + p) * BATCH];
        uint4 v0 = k4[0], v1 = k4[1];
        unsigned kv[8] = { v0.x, v0.y, v0.z, v0.w, v1.x, v1.y, v1.z, v1.w };
        float d1 = 1e30f, d2 = 1e30f;
        #pragma unroll
        for (int cc = 0; cc < BATCH; ++cc) {
            if (cc == b) continue;
            float dot = dec_f(kv[cc]);
            float d = sqrtf(fmaxf(2.0f - 2.0f * dot, 0.0f));
            if (d < d1) { d2 = d1; d1 = d; }
            else if (d < d2) { d2 = d; }
        }
        sum += 0.5f * (d1 + d2);
    }
    float s = sum * (1.0f / 12.0f);
    g_scores[idx] = s;
    atomicMax(&g_img[b], enc_f(s));
}

__global__ void bilinear_kernel(float* __restrict__ out) {
    int idx = blockIdx.x * 256 + threadIdx.x;
    if (idx >= BATCH * OUTH * OUTW) return;
    if (idx < BATCH) out[idx] = dec_f(g_img[idx]);   // scores_image

    int b = idx / (OUTH * OUTW);
    int rr = idx % (OUTH * OUTW);
    int y = rr / OUTW, x = rr % OUTW;

    const float sc = 23.0f / 335.0f;
    float fy = (float)y * sc;
    float fx = (float)x * sc;
    int y0 = (int)floorf(fy); int y1 = min(y0 + 1, PHN - 1);
    int x0 = (int)floorf(fx); int x1 = min(x0 + 1, PWN - 1);
    float wy = fy - (float)y0;
    float wx = fx - (float)x0;

    const float* s = g_scores + b * PATCHES;
    float f00 = s[y0 * PWN + x0];
    float f01 = s[y0 * PWN + x1];
    float f10 = s[y1 * PWN + x0];
    float f11 = s[y1 * PWN + x1];

    out[BATCH + idx] = f00 * (1.f - wy) * (1.f - wx) + f01 * (1.f - wy) * wx
                     + f10 * wy * (1.f - wx)         + f11 * wy * wx;
}

// ---------------- launch ----------------
typedef CUresult (*PFN_TMapEncode)(
    CUtensorMap*, CUtensorMapDataType, cuuint32_t, void*,
    const cuuint64_t*, const cuuint64_t*, const cuuint32_t*, const cuuint32_t*,
    CUtensorMapInterleave, CUtensorMapSwizzle, CUtensorMapL2promotion,
    CUtensorMapFloatOOBfill);

extern "C" void kernel_launch(void* const* d_in, const int* in_sizes, int n_in,
                              void* d_out, int out_size) {
    const float* feat = (const float*)d_in[0];
    float* out = (float*)d_out;

    // TMA descriptor: uint8 2D (2048 B x 61440 rows), box 128x144, SW128.
    static CUtensorMap tmap;
    {
        void* fn = nullptr;
        cudaDriverEntryPointQueryResult qres;
        cudaGetDriverEntryPointByVersion("cuTensorMapEncodeTiled", &fn, 12000,
                                         cudaEnableDefault, &qres);
        void* gptr = nullptr;
        cudaGetSymbolAddress(&gptr, g_featn);
        cuuint64_t dims[2]    = { (cuuint64_t)(DIM * 2), (cuuint64_t)(NRL * BATCH * PADP) };
        cuuint64_t strides[1] = { (cuuint64_t)(DIM * 2) };
        cuuint32_t box[2]     = { 128u, 144u };
        cuuint32_t estr[2]    = { 1u, 1u };
        if (fn) {
            ((PFN_TMapEncode)fn)(&tmap, CU_TENSOR_MAP_DATA_TYPE_UINT8, 2, gptr,
                                 dims, strides, box, estr,
                                 CU_TENSOR_MAP_INTERLEAVE_NONE,
                                 CU_TENSOR_MAP_SWIZZLE_128B,
                                 CU_TENSOR_MAP_L2_PROMOTION_L2_128B,
                                 CU_TENSOR_MAP_FLOAT_OOB_FILL_NONE);
        }
    }

    cudaFuncSetAttribute(gemm_max_mma, cudaFuncAttributeMaxDynamicSharedMemorySize, SMEM_DYN);

    pool_norm_kernel<<<dim3(PATCHES, BATCH, L_LAYERS), 256>>>(feat);
    gemm_max_mma<<<dim3(4, NPAIRS, NRL), NTHR, SMEM_DYN>>>(tmap);
    score_kernel<<<(BATCH * PATCHES + 127) / 128, 128>>>();
    bilinear_kernel<<<(BATCH * OUTH * OUTW + 255) / 256, 256>>>(out);
}

// round 13
// speedup vs baseline: 1.9029x; 1.9029x over previous
#include <cuda_runtime.h>
#include <cuda.h>
#include <cuda_fp16.h>
#include <cstdint>
#include <math.h>

#define L_LAYERS 4
#define BATCH    8
#define PHN      24
#define PWN      24
#define PATCHES  576
#define DIM      1024
#define NRL      12
#define NPAIRS   28
#define OUTH     336
#define OUTW     336
#define PADP     640
#define TILEM    192
#define KS       64             // k per slab (128 B fp16, SW128)
#define NSLAB    16
#define NTHR     128            // 4 warps, warp tile 96x96
#define MATB     (TILEM * 128)  // 24576
#define STAGEB   (2 * MATB)     // 49152
#define TXB      STAGEB
#define SMEM_DYN (2048 + 2 * STAGEB)   // 100352 -> 2 CTAs/SM

// ---------------- device scratch ----------------
__device__ __align__(128) __half g_featn[(size_t)NRL * BATCH * PADP * DIM];
__device__ unsigned g_keys[NRL * BATCH * PADP * BATCH];
__device__ float    g_scores[BATCH * PATCHES];
__device__ unsigned g_img[BATCH];

__device__ __forceinline__ unsigned enc_f(float x) {
    unsigned u = __float_as_uint(x);
    return (u & 0x80000000u) ? ~u : (u | 0x80000000u);
}
__device__ __forceinline__ float dec_f(unsigned k) {
    unsigned u = (k & 0x80000000u) ? (k & 0x7FFFFFFFu) : ~k;
    return __uint_as_float(u);
}
__device__ __forceinline__ uint32_t smem_u32(const void* p) {
    uint32_t a;
    asm("{ .reg .u64 t; cvta.to.shared.u64 t, %1; cvt.u32.u64 %0, t; }" : "=r"(a) : "l"(p));
    return a;
}

#define MBAR_INIT(a, n) asm volatile("mbarrier.init.shared.b64 [%0], %1;" :: "r"(a), "r"(n) : "memory")
#define MBAR_EXPECT(a, tx) asm volatile("mbarrier.arrive.expect_tx.shared.b64 _, [%0], %1;" :: "r"(a), "r"(tx) : "memory")
#define MBAR_WAIT(a, ph) do { \
    uint32_t _m = (a), _p = (ph), _d; \
    asm volatile("{ .reg .pred p; mbarrier.try_wait.parity.acquire.cta.shared::cta.b64 p, [%1], %2; selp.b32 %0,1,0,p; }" \
        : "=r"(_d) : "r"(_m), "r"(_p) : "memory"); \
    if (!_d) { asm volatile("{ .reg .pred P1; WL_%=: mbarrier.try_wait.parity.acquire.cta.shared::cta.b64 P1, [%0], %1, 0x989680; @P1 bra.uni WD_%=; bra.uni WL_%=; WD_%=: }" \
        :: "r"(_m), "r"(_p) : "memory"); } \
} while (0)

#define TMA_LOAD_2D(dst, map, cx, cy, mbar) \
    asm volatile("cp.async.bulk.tensor.2d.shared::cta.global.tile.mbarrier::complete_tx::bytes " \
        "[%0], [%1, {%2, %3}], [%4];" \
        :: "r"(dst), "l"(map), "r"(cx), "r"(cy), "r"(mbar) : "memory")

#define LDSM_X4(r0, r1, r2, r3, a) \
    asm volatile("ldmatrix.sync.aligned.m8n8.x4.shared.b16 {%0,%1,%2,%3}, [%4];" \
        : "=r"(r0), "=r"(r1), "=r"(r2), "=r"(r3) : "r"(a))

#define MMA16816H(c, a, b) \
    asm volatile("mma.sync.aligned.m16n8k16.row.col.f16.f16.f16.f16 " \
        "{%0,%1}, {%2,%3,%4,%5}, {%6,%7}, {%0,%1};" \
        : "+r"((c)[0]), "+r"((c)[1]) \
        : "r"((a)[0]), "r"((a)[1]), "r"((a)[2]), "r"((a)[3]), "r"((b)[0]), "r"((b)[1]))

// ---------------- pool + normalize -> fp16, also clears g_keys / g_img ------
__global__ void pool_norm_kernel(const float* __restrict__ feat) {
    int p = blockIdx.x, b = blockIdx.y, l = blockIdx.z;
    int ph = p / PWN, pw = p % PWN;
    int t = threadIdx.x;
    int d0 = t * 4;

    // fold init: clear g_keys (491520 uints over first 1920 blocks) + g_img
    {
        int lin = (l * BATCH + b) * PATCHES + p;
        if (lin < (NRL * BATCH * PADP * BATCH) / 256)
            g_keys[lin * 256 + t] = 0u;
        if (lin == 0 && t < BATCH) g_img[t] = 0u;
    }

    const float* base = feat + ((size_t)(l * BATCH + b) * PATCHES) * DIM;

    float4 s5 = make_float4(0.f, 0.f, 0.f, 0.f);
    float4 s3 = make_float4(0.f, 0.f, 0.f, 0.f);
    float4 s1 = make_float4(0.f, 0.f, 0.f, 0.f);

    #pragma unroll
    for (int dy = -2; dy <= 2; ++dy) {
        int y = ph + dy;
        if ((unsigned)y >= (unsigned)PHN) continue;
        #pragma unroll
        for (int dx = -2; dx <= 2; ++dx) {
            int x = pw + dx;
            if ((unsigned)x >= (unsigned)PWN) continue;
            const float4 v = *(const float4*)(base + (size_t)(y * PWN + x) * DIM + d0);
            s5.x += v.x; s5.y += v.y; s5.z += v.z; s5.w += v.w;
            if (dy >= -1 && dy <= 1 && dx >= -1 && dx <= 1) {
                s3.x += v.x; s3.y += v.y; s3.z += v.z; s3.w += v.w;
                if (dy == 0 && dx == 0) s1 = v;
            }
        }
    }
    s3.x *= (1.f/9.f);  s3.y *= (1.f/9.f);  s3.z *= (1.f/9.f);  s3.w *= (1.f/9.f);
    s5.x *= (1.f/25.f); s5.y *= (1.f/25.f); s5.z *= (1.f/25.f); s5.w *= (1.f/25.f);

    float q1 = s1.x*s1.x + s1.y*s1.y + s1.z*s1.z + s1.w*s1.w;
    float q3 = s3.x*s3.x + s3.y*s3.y + s3.z*s3.z + s3.w*s3.w;
    float q5 = s5.x*s5.x + s5.y*s5.y + s5.z*s5.z + s5.w*s5.w;
    #pragma unroll
    for (int o = 16; o > 0; o >>= 1) {
        q1 += __shfl_xor_sync(0xffffffffu, q1, o);
        q3 += __shfl_xor_sync(0xffffffffu, q3, o);
        q5 += __shfl_xor_sync(0xffffffffu, q5, o);
    }
    __shared__ float ws[3][8];
    __shared__ float rn[3];
    if ((t & 31) == 0) { ws[0][t >> 5] = q1; ws[1][t >> 5] = q3; ws[2][t >> 5] = q5; }
    __syncthreads();
    if (t < 3) {
        float x = 0.f;
        #pragma unroll
        for (int w = 0; w < 8; ++w) x += ws[t][w];
        rn[t] = rsqrtf(x);
    }
    __syncthreads();

    float4 vv[3] = { s1, s3, s5 };
    #pragma unroll
    for (int ri = 0; ri < 3; ++ri) {
        float r = rn[ri];
        __half2 lo = __floats2half2_rn(vv[ri].x * r, vv[ri].y * r);
        __half2 hi = __floats2half2_rn(vv[ri].z * r, vv[ri].w * r);
        uint2 pk = make_uint2(*(unsigned*)&lo, *(unsigned*)&hi);
        int z = ri * 4 + l;
        *(uint2*)(g_featn + ((size_t)(z * BATCH + b) * PADP + p) * DIM + d0) = pk;
    }
}

// ---------------- TMA + fp16 mma fused GEMM + bidirectional max --------------
// CTA tile 192x192, 4 warps (2x2) of 96x96, K slabs of 64 (SW128), 2-stage, 2 CTAs/SM.
__global__ void __launch_bounds__(NTHR, 2) gemm_max_mma(const __grid_constant__ CUtensorMap tmap) {
    extern __shared__ __align__(16) char dsm[];
    uint32_t sraw = smem_u32(dsm);
    uint32_t ub   = (sraw + 1023) & ~1023u;
    uint32_t sstg = ub + 1024;

    int t = threadIdx.x;
    int wid = t >> 5, lane = t & 31;
    int warp_m = wid & 1;
    int warp_n = wid >> 1;

    int tile = blockIdx.x;
    int ti = tile / 3, tj = tile % 3;
    int pair = blockIdx.y, rl = blockIdx.z;

    int b = 0, rem = pair;
    #pragma unroll
    for (int bb = 0; bb < 7; ++bb) {
        int cnt = 7 - bb;
        if (rem < cnt) { b = bb; break; }
        rem -= cnt;
    }
    int c = b + 1 + rem;

    int rowA = (rl * BATCH + b) * PADP + ti * TILEM;
    int rowB = (rl * BATCH + c) * PADP + tj * TILEM;

    if (t == 0) {
        MBAR_INIT(ub, 1); MBAR_INIT(ub + 8, 1);
        asm volatile("fence.proxy.async.shared::cta;" ::: "memory");
    }
    __syncthreads();
    if (t == 0) {
        #pragma unroll
        for (int s = 0; s < 2; ++s) {
            MBAR_EXPECT(ub + s * 8, TXB);
            TMA_LOAD_2D(sstg + s * STAGEB,        &tmap, s * 128, rowA, ub + s * 8);
            TMA_LOAD_2D(sstg + s * STAGEB + MATB, &tmap, s * 128, rowB, ub + s * 8);
        }
    }

    uint32_t acc[6][12][2];
    #pragma unroll
    for (int mi = 0; mi < 6; ++mi)
        #pragma unroll
        for (int ni = 0; ni < 12; ++ni) { acc[mi][ni][0] = 0u; acc[mi][ni][1] = 0u; }

    // SW128 swizzle in a 128B-wide box: byte col c at row r -> c ^ ((r&7)<<4)
    int rA = warp_m * 96 + (lane & 15);
    uint32_t xorA = (uint32_t)((rA & 7) << 4);
    uint32_t abase = (uint32_t)(rA * 128);
    uint32_t koA[4];
    #pragma unroll
    for (int ks = 0; ks < 4; ++ks)
        koA[ks] = (uint32_t)((ks * 32 + (lane >> 4) * 16)) ^ xorA;

    int rB = warp_n * 96 + (lane >> 4) * 8 + (lane & 7);
    uint32_t xorB = (uint32_t)((rB & 7) << 4);
    uint32_t bbase = (uint32_t)(MATB + rB * 128);
    uint32_t koB[4];
    #pragma unroll
    for (int ks = 0; ks < 4; ++ks)
        koB[ks] = (uint32_t)((ks * 32 + ((lane >> 3) & 1) * 16)) ^ xorB;

    for (int kc = 0; kc < NSLAB; ++kc) {
        int st = kc & 1;
        MBAR_WAIT(ub + st * 8, (kc >> 1) & 1);

        uint32_t Sb = sstg + st * STAGEB;

        #pragma unroll
        for (int ks = 0; ks < 4; ++ks) {
            uint32_t afr[6][4];
            #pragma unroll
            for (int mi = 0; mi < 6; ++mi)
                LDSM_X4(afr[mi][0], afr[mi][1], afr[mi][2], afr[mi][3],
                        Sb + abase + mi * 2048 + koA[ks]);
            uint32_t bfr[12][2];
            #pragma unroll
            for (int np = 0; np < 6; ++np)
                LDSM_X4(bfr[np * 2][0], bfr[np * 2][1], bfr[np * 2 + 1][0], bfr[np * 2 + 1][1],
                        Sb + bbase + np * 2048 + koB[ks]);
            #pragma unroll
            for (int mi = 0; mi < 6; ++mi)
                #pragma unroll
                for (int ni = 0; ni < 12; ++ni)
                    MMA16816H(acc[mi][ni], afr[mi], bfr[ni]);
        }

        __syncthreads();   // all warps finished reading stage st
        if (t == 0 && kc + 2 < NSLAB) {
            MBAR_EXPECT(ub + st * 8, TXB);
            TMA_LOAD_2D(Sb,        &tmap, (kc + 2) * 128, rowA, ub + st * 8);
            TMA_LOAD_2D(Sb + MATB, &tmap, (kc + 2) * 128, rowB, ub + st * 8);
        }
    }

    // ---------------- epilogue: bidirectional max ----------------
    // last slab read stage 1; stage-0 region (sstg) is free.
    float* rowsmem = (float*)(dsm + (sstg - sraw));          // [2][192] by warp_n
    float* colsmem = rowsmem + 2 * 192;                      // [2][192] by warp_m

    #pragma unroll
    for (int mi = 0; mi < 6; ++mi) {
        __half2 h0 = __float2half2_rn(-60000.f), h1 = h0;
        #pragma unroll
        for (int ni = 0; ni < 12; ++ni) {
            h0 = __hmax2(h0, *(__half2*)&acc[mi][ni][0]);
            h1 = __hmax2(h1, *(__half2*)&acc[mi][ni][1]);
        }
        float rm0 = fmaxf(__low2float(h0), __high2float(h0));
        float rm1 = fmaxf(__low2float(h1), __high2float(h1));
        #pragma unroll
        for (int o = 1; o < 4; o <<= 1) {
            rm0 = fmaxf(rm0, __shfl_xor_sync(0xffffffffu, rm0, o));
            rm1 = fmaxf(rm1, __shfl_xor_sync(0xffffffffu, rm1, o));
        }
        if ((lane & 3) == 0) {
            int lr = warp_m * 96 + mi * 16 + (lane >> 2);
            rowsmem[warp_n * 192 + lr]     = rm0;
            rowsmem[warp_n * 192 + lr + 8] = rm1;
        }
    }

    #pragma unroll
    for (int ni = 0; ni < 12; ++ni) {
        __half2 hm = __float2half2_rn(-60000.f);
        #pragma unroll
        for (int mi = 0; mi < 6; ++mi) {
            hm = __hmax2(hm, *(__half2*)&acc[mi][ni][0]);
            hm = __hmax2(hm, *(__half2*)&acc[mi][ni][1]);
        }
        float cm0 = __low2float(hm);
        float cm1 = __high2float(hm);
        #pragma unroll
        for (int o = 4; o < 32; o <<= 1) {
            cm0 = fmaxf(cm0, __shfl_xor_sync(0xffffffffu, cm0, o));
            cm1 = fmaxf(cm1, __shfl_xor_sync(0xffffffffu, cm1, o));
        }
        if (lane < 4) {
            int lc = warp_n * 96 + ni * 8 + lane * 2;
            colsmem[warp_m * 192 + lc]     = cm0;
            colsmem[warp_m * 192 + lc + 1] = cm1;
        }
    }
    __syncthreads();

    for (int idx = t; idx < 192; idx += NTHR) {
        float mr = fmaxf(rowsmem[idx], rowsmem[192 + idx]);
        int p = ti * TILEM + idx;
        atomicMax(&g_keys[((size_t)(rl * BATCH + b) * PADP + p) * BATCH + c], enc_f(mr));
        float mc = fmaxf(colsmem[idx], colsmem[192 + idx]);
        int q = tj * TILEM + idx;
        atomicMax(&g_keys[((size_t)(rl * BATCH + c) * PADP + q) * BATCH + b], enc_f(mc));
    }
}

// ---------------- score (+ fused image max) / bilinear ----------------
__global__ void score_kernel() {
    int idx = blockIdx.x * 128 + threadIdx.x;
    if (idx >= BATCH * PATCHES) return;
    int b = idx / PATCHES;
    int p = idx % PATCHES;

    float sum = 0.f;
    #pragma unroll
    for (int rl = 0; rl < NRL; ++rl) {
        const uint4* k4 = (const uint4*)&g_keys[((size_t)(rl * BATCH + b) * PADP + p) * BATCH];
        uint4 v0 = k4[0], v1 = k4[1];
        unsigned kv[8] = { v0.x, v0.y, v0.z, v0.w, v1.x, v1.y, v1.z, v1.w };
        float d1 = 1e30f, d2 = 1e30f;
        #pragma unroll
        for (int cc = 0; cc < BATCH; ++cc) {
            if (cc == b) continue;
            float dot = dec_f(kv[cc]);
            float d = sqrtf(fmaxf(2.0f - 2.0f * dot, 0.0f));
            if (d < d1) { d2 = d1; d1 = d; }
            else if (d < d2) { d2 = d; }
        }
        sum += 0.5f * (d1 + d2);
    }
    float s = sum * (1.0f / 12.0f);
    g_scores[idx] = s;
    atomicMax(&g_img[b], enc_f(s));
}

__global__ void bilinear_kernel(float* __restrict__ out) {
    int idx = blockIdx.x * 256 + threadIdx.x;
    if (idx >= BATCH * OUTH * OUTW) return;
    if (idx < BATCH) out[idx] = dec_f(g_img[idx]);   // scores_image

    int b = idx / (OUTH * OUTW);
    int rr = idx % (OUTH * OUTW);
    int y = rr / OUTW, x = rr % OUTW;

    const float sc = 23.0f / 335.0f;
    float fy = (float)y * sc;
    float fx = (float)x * sc;
    int y0 = (int)floorf(fy); int y1 = min(y0 + 1, PHN - 1);
    int x0 = (int)floorf(fx); int x1 = min(x0 + 1, PWN - 1);
    float wy = fy - (float)y0;
    float wx = fx - (float)x0;

    const float* s = g_scores + b * PATCHES;
    float f00 = s[y0 * PWN + x0];
    float f01 = s[y0 * PWN + x1];
    float f10 = s[y1 * PWN + x0];
    float f11 = s[y1 * PWN + x1];

    out[BATCH + idx] = f00 * (1.f - wy) * (1.f - wx) + f01 * (1.f - wy) * wx
                     + f10 * wy * (1.f - wx)         + f11 * wy * wx;
}

// ---------------- launch ----------------
typedef CUresult (*PFN_TMapEncode)(
    CUtensorMap*, CUtensorMapDataType, cuuint32_t, void*,
    const cuuint64_t*, const cuuint64_t*, const cuuint32_t*, const cuuint32_t*,
    CUtensorMapInterleave, CUtensorMapSwizzle, CUtensorMapL2promotion,
    CUtensorMapFloatOOBfill);

extern "C" void kernel_launch(void* const* d_in, const int* in_sizes, int n_in,
                              void* d_out, int out_size) {
    const float* feat = (const float*)d_in[0];
    float* out = (float*)d_out;

    // TMA descriptor: uint8 2D (2048 B x 61440 rows), box 128x192, SW128.
    static CUtensorMap tmap;
    {
        void* fn = nullptr;
        cudaDriverEntryPointQueryResult qres;
        cudaGetDriverEntryPointByVersion("cuTensorMapEncodeTiled", &fn, 12000,
                                         cudaEnableDefault, &qres);
        void* gptr = nullptr;
        cudaGetSymbolAddress(&gptr, g_featn);
        cuuint64_t dims[2]    = { (cuuint64_t)(DIM * 2), (cuuint64_t)(NRL * BATCH * PADP) };
        cuuint64_t strides[1] = { (cuuint64_t)(DIM * 2) };
        cuuint32_t box[2]     = { 128u, (cuuint32_t)TILEM };
        cuuint32_t estr[2]    = { 1u, 1u };
        if (fn) {
            ((PFN_TMapEncode)fn)(&tmap, CU_TENSOR_MAP_DATA_TYPE_UINT8, 2, gptr,
                                 dims, strides, box, estr,
                                 CU_TENSOR_MAP_INTERLEAVE_NONE,
                                 CU_TENSOR_MAP_SWIZZLE_128B,
                                 CU_TENSOR_MAP_L2_PROMOTION_L2_128B,
                                 CU_TENSOR_MAP_FLOAT_OOB_FILL_NONE);
        }
    }

    cudaFuncSetAttribute(gemm_max_mma, cudaFuncAttributeMaxDynamicSharedMemorySize, SMEM_DYN);

    pool_norm_kernel<<<dim3(PATCHES, BATCH, L_LAYERS), 256>>>(feat);
    gemm_max_mma<<<dim3(9, NPAIRS, NRL), NTHR, SMEM_DYN>>>(tmap);
    score_kernel<<<(BATCH * PATCHES + 127) / 128, 128>>>();
    bilinear_kernel<<<(BATCH * OUTH * OUTW + 255) / 256, 256>>>(out);
}

// round 14
// speedup vs baseline: 2.0217x; 1.0624x over previous
#include <cuda_runtime.h>
#include <cuda.h>
#include <cuda_fp16.h>
#include <cstdint>
#include <math.h>

#define L_LAYERS 4
#define BATCH    8
#define PHN      24
#define PWN      24
#define PATCHES  576
#define DIM      1024
#define NRL      12
#define NPAIRS   28
#define OUTH     336
#define OUTW     336
#define PADP     640
#define TILEM    192
#define KS       64             // k per slab (128 B fp16, SW128)
#define NSLAB    16
#define NTHR     128            // 4 warps, warp tile 96x96
#define MATB     (TILEM * 128)  // 24576
#define STAGEB   (2 * MATB)     // 49152
#define TXB      STAGEB
#define SMEM_DYN (2048 + 2 * STAGEB)   // 100352 -> 2 CTAs/SM

// ---------------- device scratch ----------------
__device__ __align__(128) __half g_featn[(size_t)NRL * BATCH * PADP * DIM];
__device__ unsigned g_keys[NRL * BATCH * PADP * BATCH];
__device__ float    g_scores[BATCH * PATCHES];
__device__ unsigned g_img[BATCH];

__device__ __forceinline__ unsigned enc_f(float x) {
    unsigned u = __float_as_uint(x);
    return (u & 0x80000000u) ? ~u : (u | 0x80000000u);
}
__device__ __forceinline__ float dec_f(unsigned k) {
    unsigned u = (k & 0x80000000u) ? (k & 0x7FFFFFFFu) : ~k;
    return __uint_as_float(u);
}
__device__ __forceinline__ uint32_t smem_u32(const void* p) {
    uint32_t a;
    asm("{ .reg .u64 t; cvta.to.shared.u64 t, %1; cvt.u32.u64 %0, t; }" : "=r"(a) : "l"(p));
    return a;
}

#define MBAR_INIT(a, n) asm volatile("mbarrier.init.shared.b64 [%0], %1;" :: "r"(a), "r"(n) : "memory")
#define MBAR_EXPECT(a, tx) asm volatile("mbarrier.arrive.expect_tx.shared.b64 _, [%0], %1;" :: "r"(a), "r"(tx) : "memory")
#define MBAR_WAIT(a, ph) do { \
    uint32_t _m = (a), _p = (ph), _d; \
    asm volatile("{ .reg .pred p; mbarrier.try_wait.parity.acquire.cta.shared::cta.b64 p, [%1], %2; selp.b32 %0,1,0,p; }" \
        : "=r"(_d) : "r"(_m), "r"(_p) : "memory"); \
    if (!_d) { asm volatile("{ .reg .pred P1; WL_%=: mbarrier.try_wait.parity.acquire.cta.shared::cta.b64 P1, [%0], %1, 0x989680; @P1 bra.uni WD_%=; bra.uni WL_%=; WD_%=: }" \
        :: "r"(_m), "r"(_p) : "memory"); } \
} while (0)

#define TMA_LOAD_2D(dst, map, cx, cy, mbar) \
    asm volatile("cp.async.bulk.tensor.2d.shared::cta.global.tile.mbarrier::complete_tx::bytes " \
        "[%0], [%1, {%2, %3}], [%4];" \
        :: "r"(dst), "l"(map), "r"(cx), "r"(cy), "r"(mbar) : "memory")

#define LDSM_X4(r0, r1, r2, r3, a) \
    asm volatile("ldmatrix.sync.aligned.m8n8.x4.shared.b16 {%0,%1,%2,%3}, [%4];" \
        : "=r"(r0), "=r"(r1), "=r"(r2), "=r"(r3) : "r"(a))

#define MMA16816H(c, a, b) \
    asm volatile("mma.sync.aligned.m16n8k16.row.col.f16.f16.f16.f16 " \
        "{%0,%1}, {%2,%3,%4,%5}, {%6,%7}, {%0,%1};" \
        : "+r"((c)[0]), "+r"((c)[1]) \
        : "r"((a)[0]), "r"((a)[1]), "r"((a)[2]), "r"((a)[3]), "r"((b)[0]), "r"((b)[1]))

// ---------------- pool + normalize -> fp16 (4 patches/block) ----------------
// grid: (24 ph * 6 pwg, BATCH, L_LAYERS) = (144, 8, 4); block 256 (thread = 4 dims).
__global__ void __launch_bounds__(256) pool_norm_kernel(const float* __restrict__ feat) {
    int bx = blockIdx.x, b = blockIdx.y, l = blockIdx.z;
    int ph = bx / 6, pwg = bx % 6;
    int pw0 = pwg * 4;
    int t = threadIdx.x;
    int d0 = t * 4;

    // fold init: clear g_keys (491520 uints over first 1920 linear blocks) + g_img
    {
        int lin = (l * BATCH + b) * 144 + bx;
        if (lin < (NRL * BATCH * PADP * BATCH) / 256)
            g_keys[lin * 256 + t] = 0u;
        if (lin == 0 && t < BATCH) g_img[t] = 0u;
    }

    const float* base = feat + ((size_t)(l * BATCH + b) * PATCHES) * DIM;

    float4 s1[4], s3[4], s5[4];
    #pragma unroll
    for (int j = 0; j < 4; ++j) {
        s1[j] = make_float4(0.f, 0.f, 0.f, 0.f);
        s3[j] = make_float4(0.f, 0.f, 0.f, 0.f);
        s5[j] = make_float4(0.f, 0.f, 0.f, 0.f);
    }

    #pragma unroll
    for (int dy = -2; dy <= 2; ++dy) {
        int y = ph + dy;
        if ((unsigned)y >= (unsigned)PHN) continue;
        bool in3y = (dy >= -1 && dy <= 1);
        bool in1y = (dy == 0);
        #pragma unroll
        for (int xi = 0; xi < 8; ++xi) {
            int x = pw0 - 2 + xi;
            if ((unsigned)x >= (unsigned)PWN) continue;
            const float4 v = *(const float4*)(base + (size_t)(y * PWN + x) * DIM + d0);
            #pragma unroll
            for (int j = 0; j < 4; ++j) {
                int dxi = xi - (j + 2);
                if (dxi >= -2 && dxi <= 2) {
                    s5[j].x += v.x; s5[j].y += v.y; s5[j].z += v.z; s5[j].w += v.w;
                    if (in3y && dxi >= -1 && dxi <= 1) {
                        s3[j].x += v.x; s3[j].y += v.y; s3[j].z += v.z; s3[j].w += v.w;
                        if (in1y && dxi == 0) s1[j] = v;
                    }
                }
            }
        }
    }
    #pragma unroll
    for (int j = 0; j < 4; ++j) {
        s3[j].x *= (1.f/9.f);  s3[j].y *= (1.f/9.f);  s3[j].z *= (1.f/9.f);  s3[j].w *= (1.f/9.f);
        s5[j].x *= (1.f/25.f); s5[j].y *= (1.f/25.f); s5[j].z *= (1.f/25.f); s5[j].w *= (1.f/25.f);
    }

    // 12 squared-norm reductions: q[ri*4 + j]
    float q[12];
    #pragma unroll
    for (int j = 0; j < 4; ++j) {
        q[0 + j] = s1[j].x*s1[j].x + s1[j].y*s1[j].y + s1[j].z*s1[j].z + s1[j].w*s1[j].w;
        q[4 + j] = s3[j].x*s3[j].x + s3[j].y*s3[j].y + s3[j].z*s3[j].z + s3[j].w*s3[j].w;
        q[8 + j] = s5[j].x*s5[j].x + s5[j].y*s5[j].y + s5[j].z*s5[j].z + s5[j].w*s5[j].w;
    }
    #pragma unroll
    for (int k = 0; k < 12; ++k)
        #pragma unroll
        for (int o = 16; o > 0; o >>= 1)
            q[k] += __shfl_xor_sync(0xffffffffu, q[k], o);

    __shared__ float ws[8][12];
    __shared__ float rn[12];
    if ((t & 31) == 0)
        #pragma unroll
        for (int k = 0; k < 12; ++k) ws[t >> 5][k] = q[k];
    __syncthreads();
    if (t < 12) {
        float x = 0.f;
        #pragma unroll
        for (int w = 0; w < 8; ++w) x += ws[w][t];
        rn[t] = rsqrtf(x);
    }
    __syncthreads();

    #pragma unroll
    for (int ri = 0; ri < 3; ++ri) {
        int z = ri * 4 + l;
        #pragma unroll
        for (int j = 0; j < 4; ++j) {
            float4 v = (ri == 0) ? s1[j] : (ri == 1) ? s3[j] : s5[j];
            float r = rn[ri * 4 + j];
            __half2 lo = __floats2half2_rn(v.x * r, v.y * r);
            __half2 hi = __floats2half2_rn(v.z * r, v.w * r);
            uint2 pk = make_uint2(*(unsigned*)&lo, *(unsigned*)&hi);
            int p = ph * PWN + pw0 + j;
            *(uint2*)(g_featn + ((size_t)(z * BATCH + b) * PADP + p) * DIM + d0) = pk;
        }
    }
}

// ---------------- TMA + fp16 mma fused GEMM + bidirectional max --------------
// CTA tile 192x192, 4 warps (2x2) of 96x96, K slabs of 64 (SW128), 2-stage, 2 CTAs/SM.
__global__ void __launch_bounds__(NTHR, 2) gemm_max_mma(const __grid_constant__ CUtensorMap tmap) {
    extern __shared__ __align__(16) char dsm[];
    uint32_t sraw = smem_u32(dsm);
    uint32_t ub   = (sraw + 1023) & ~1023u;
    uint32_t sstg = ub + 1024;

    int t = threadIdx.x;
    int wid = t >> 5, lane = t & 31;
    int warp_m = wid & 1;
    int warp_n = wid >> 1;

    int tile = blockIdx.x;
    int ti = tile / 3, tj = tile % 3;
    int pair = blockIdx.y, rl = blockIdx.z;

    int b = 0, rem = pair;
    #pragma unroll
    for (int bb = 0; bb < 7; ++bb) {
        int cnt = 7 - bb;
        if (rem < cnt) { b = bb; break; }
        rem -= cnt;
    }
    int c = b + 1 + rem;

    int rowA = (rl * BATCH + b) * PADP + ti * TILEM;
    int rowB = (rl * BATCH + c) * PADP + tj * TILEM;

    if (t == 0) {
        MBAR_INIT(ub, 1); MBAR_INIT(ub + 8, 1);
        asm volatile("fence.proxy.async.shared::cta;" ::: "memory");
    }
    __syncthreads();
    if (t == 0) {
        #pragma unroll
        for (int s = 0; s < 2; ++s) {
            MBAR_EXPECT(ub + s * 8, TXB);
            TMA_LOAD_2D(sstg + s * STAGEB,        &tmap, s * 128, rowA, ub + s * 8);
            TMA_LOAD_2D(sstg + s * STAGEB + MATB, &tmap, s * 128, rowB, ub + s * 8);
        }
    }

    uint32_t acc[6][12][2];
    #pragma unroll
    for (int mi = 0; mi < 6; ++mi)
        #pragma unroll
        for (int ni = 0; ni < 12; ++ni) { acc[mi][ni][0] = 0u; acc[mi][ni][1] = 0u; }

    // SW128 swizzle in a 128B-wide box: byte col c at row r -> c ^ ((r&7)<<4)
    int rA = warp_m * 96 + (lane & 15);
    uint32_t xorA = (uint32_t)((rA & 7) << 4);
    uint32_t abase = (uint32_t)(rA * 128);
    uint32_t koA[4];
    #pragma unroll
    for (int ks = 0; ks < 4; ++ks)
        koA[ks] = (uint32_t)((ks * 32 + (lane >> 4) * 16)) ^ xorA;

    int rB = warp_n * 96 + (lane >> 4) * 8 + (lane & 7);
    uint32_t xorB = (uint32_t)((rB & 7) << 4);
    uint32_t bbase = (uint32_t)(MATB + rB * 128);
    uint32_t koB[4];
    #pragma unroll
    for (int ks = 0; ks < 4; ++ks)
        koB[ks] = (uint32_t)((ks * 32 + ((lane >> 3) & 1) * 16)) ^ xorB;

    for (int kc = 0; kc < NSLAB; ++kc) {
        int st = kc & 1;
        MBAR_WAIT(ub + st * 8, (kc >> 1) & 1);

        uint32_t Sb = sstg + st * STAGEB;

        #pragma unroll
        for (int ks = 0; ks < 4; ++ks) {
            uint32_t afr[6][4];
            #pragma unroll
            for (int mi = 0; mi < 6; ++mi)
                LDSM_X4(afr[mi][0], afr[mi][1], afr[mi][2], afr[mi][3],
                        Sb + abase + mi * 2048 + koA[ks]);
            uint32_t bfr[12][2];
            #pragma unroll
            for (int np = 0; np < 6; ++np)
                LDSM_X4(bfr[np * 2][0], bfr[np * 2][1], bfr[np * 2 + 1][0], bfr[np * 2 + 1][1],
                        Sb + bbase + np * 2048 + koB[ks]);
            #pragma unroll
            for (int mi = 0; mi < 6; ++mi)
                #pragma unroll
                for (int ni = 0; ni < 12; ++ni)
                    MMA16816H(acc[mi][ni], afr[mi], bfr[ni]);
        }

        __syncthreads();   // all warps finished reading stage st
        if (t == 0 && kc + 2 < NSLAB) {
            MBAR_EXPECT(ub + st * 8, TXB);
            TMA_LOAD_2D(Sb,        &tmap, (kc + 2) * 128, rowA, ub + st * 8);
            TMA_LOAD_2D(Sb + MATB, &tmap, (kc + 2) * 128, rowB, ub + st * 8);
        }
    }

    // ---------------- epilogue: bidirectional max ----------------
    float* rowsmem = (float*)(dsm + (sstg - sraw));          // [2][192] by warp_n
    float* colsmem = rowsmem + 2 * 192;                      // [2][192] by warp_m

    #pragma unroll
    for (int mi = 0; mi < 6; ++mi) {
        __half2 h0 = __float2half2_rn(-60000.f), h1 = h0;
        #pragma unroll
        for (int ni = 0; ni < 12; ++ni) {
            h0 = __hmax2(h0, *(__half2*)&acc[mi][ni][0]);
            h1 = __hmax2(h1, *(__half2*)&acc[mi][ni][1]);
        }
        float rm0 = fmaxf(__low2float(h0), __high2float(h0));
        float rm1 = fmaxf(__low2float(h1), __high2float(h1));
        #pragma unroll
        for (int o = 1; o < 4; o <<= 1) {
            rm0 = fmaxf(rm0, __shfl_xor_sync(0xffffffffu, rm0, o));
            rm1 = fmaxf(rm1, __shfl_xor_sync(0xffffffffu, rm1, o));
        }
        if ((lane & 3) == 0) {
            int lr = warp_m * 96 + mi * 16 + (lane >> 2);
            rowsmem[warp_n * 192 + lr]     = rm0;
            rowsmem[warp_n * 192 + lr + 8] = rm1;
        }
    }

    #pragma unroll
    for (int ni = 0; ni < 12; ++ni) {
        __half2 hm = __float2half2_rn(-60000.f);
        #pragma unroll
        for (int mi = 0; mi < 6; ++mi) {
            hm = __hmax2(hm, *(__half2*)&acc[mi][ni][0]);
            hm = __hmax2(hm, *(__half2*)&acc[mi][ni][1]);
        }
        float cm0 = __low2float(hm);
        float cm1 = __high2float(hm);
        #pragma unroll
        for (int o = 4; o < 32; o <<= 1) {
            cm0 = fmaxf(cm0, __shfl_xor_sync(0xffffffffu, cm0, o));
            cm1 = fmaxf(cm1, __shfl_xor_sync(0xffffffffu, cm1, o));
        }
        if (lane < 4) {
            int lc = warp_n * 96 + ni * 8 + lane * 2;
            colsmem[warp_m * 192 + lc]     = cm0;
            colsmem[warp_m * 192 + lc + 1] = cm1;
        }
    }
    __syncthreads();

    for (int idx = t; idx < 192; idx += NTHR) {
        float mr = fmaxf(rowsmem[idx], rowsmem[192 + idx]);
        int p = ti * TILEM + idx;
        atomicMax(&g_keys[((size_t)(rl * BATCH + b) * PADP + p) * BATCH + c], enc_f(mr));
        float mc = fmaxf(colsmem[idx], colsmem[192 + idx]);
        int q = tj * TILEM + idx;
        atomicMax(&g_keys[((size_t)(rl * BATCH + c) * PADP + q) * BATCH + b], enc_f(mc));
    }
}

// ---------------- score (+ fused image max), rl-parallel ----------------
// block 128 = 32 idx x 4 rl-lanes (3 rl each); grid 144.
__global__ void score_kernel() {
    int t = threadIdx.x;
    int idx = blockIdx.x * 32 + (t >> 2);
    int rlg = t & 3;
    if (idx >= BATCH * PATCHES) return;
    int b = idx / PATCHES;
    int p = idx % PATCHES;

    float sum = 0.f;
    #pragma unroll
    for (int r = 0; r < 3; ++r) {
        int rl = rlg * 3 + r;
        const uint4* k4 = (const uint4*)&g_keys[((size_t)(rl * BATCH + b) * PADP + p) * BATCH];
        uint4 v0 = k4[0], v1 = k4[1];
        unsigned kv[8] = { v0.x, v0.y, v0.z, v0.w, v1.x, v1.y, v1.z, v1.w };
        float d1 = 1e30f, d2 = 1e30f;
        #pragma unroll
        for (int cc = 0; cc < BATCH; ++cc) {
            if (cc == b) continue;
            float dot = dec_f(kv[cc]);
            float d = sqrtf(fmaxf(2.0f - 2.0f * dot, 0.0f));
            if (d < d1) { d2 = d1; d1 = d; }
            else if (d < d2) { d2 = d; }
        }
        sum += 0.5f * (d1 + d2);
    }
    sum += __shfl_xor_sync(0xffffffffu, sum, 1);
    sum += __shfl_xor_sync(0xffffffffu, sum, 2);
    if (rlg == 0) {
        float s = sum * (1.0f / 12.0f);
        g_scores[idx] = s;
        atomicMax(&g_img[b], enc_f(s));
    }
}

__global__ void bilinear_kernel(float* __restrict__ out) {
    int idx = blockIdx.x * 256 + threadIdx.x;
    if (idx >= BATCH * OUTH * OUTW) return;
    if (idx < BATCH) out[idx] = dec_f(g_img[idx]);   // scores_image

    int b = idx / (OUTH * OUTW);
    int rr = idx % (OUTH * OUTW);
    int y = rr / OUTW, x = rr % OUTW;

    const float sc = 23.0f / 335.0f;
    float fy = (float)y * sc;
    float fx = (float)x * sc;
    int y0 = (int)floorf(fy); int y1 = min(y0 + 1, PHN - 1);
    int x0 = (int)floorf(fx); int x1 = min(x0 + 1, PWN - 1);
    float wy = fy - (float)y0;
    float wx = fx - (float)x0;

    const float* s = g_scores + b * PATCHES;
    float f00 = s[y0 * PWN + x0];
    float f01 = s[y0 * PWN + x1];
    float f10 = s[y1 * PWN + x0];
    float f11 = s[y1 * PWN + x1];

    out[BATCH + idx] = f00 * (1.f - wy) * (1.f - wx) + f01 * (1.f - wy) * wx
                     + f10 * wy * (1.f - wx)         + f11 * wy * wx;
}

// ---------------- launch ----------------
typedef CUresult (*PFN_TMapEncode)(
    CUtensorMap*, CUtensorMapDataType, cuuint32_t, void*,
    const cuuint64_t*, const cuuint64_t*, const cuuint32_t*, const cuuint32_t*,
    CUtensorMapInterleave, CUtensorMapSwizzle, CUtensorMapL2promotion,
    CUtensorMapFloatOOBfill);

extern "C" void kernel_launch(void* const* d_in, const int* in_sizes, int n_in,
                              void* d_out, int out_size) {
    const float* feat = (const float*)d_in[0];
    float* out = (float*)d_out;

    // TMA descriptor: uint8 2D (2048 B x 61440 rows), box 128x192, SW128.
    static CUtensorMap tmap;
    {
        void* fn = nullptr;
        cudaDriverEntryPointQueryResult qres;
        cudaGetDriverEntryPointByVersion("cuTensorMapEncodeTiled", &fn, 12000,
                                         cudaEnableDefault, &qres);
        void* gptr = nullptr;
        cudaGetSymbolAddress(&gptr, g_featn);
        cuuint64_t dims[2]    = { (cuuint64_t)(DIM * 2), (cuuint64_t)(NRL * BATCH * PADP) };
        cuuint64_t strides[1] = { (cuuint64_t)(DIM * 2) };
        cuuint32_t box[2]     = { 128u, (cuuint32_t)TILEM };
        cuuint32_t estr[2]    = { 1u, 1u };
        if (fn) {
            ((PFN_TMapEncode)fn)(&tmap, CU_TENSOR_MAP_DATA_TYPE_UINT8, 2, gptr,
                                 dims, strides, box, estr,
                                 CU_TENSOR_MAP_INTERLEAVE_NONE,
                                 CU_TENSOR_MAP_SWIZZLE_128B,
                                 CU_TENSOR_MAP_L2_PROMOTION_L2_128B,
                                 CU_TENSOR_MAP_FLOAT_OOB_FILL_NONE);
        }
    }

    cudaFuncSetAttribute(gemm_max_mma, cudaFuncAttributeMaxDynamicSharedMemorySize, SMEM_DYN);

    pool_norm_kernel<<<dim3(144, BATCH, L_LAYERS), 256>>>(feat);
    gemm_max_mma<<<dim3(9, NPAIRS, NRL), NTHR, SMEM_DYN>>>(tmap);
    score_kernel<<<144, 128>>>();
    bilinear_kernel<<<(BATCH * OUTH * OUTW + 255) / 256, 256>>>(out);
}

// round 16
// speedup vs baseline: 2.0287x; 1.0034x over previous
#include <cuda_runtime.h>
#include <cuda.h>
#include <cuda_fp16.h>
#include <cstdint>
#include <math.h>

#define L_LAYERS 4
#define BATCH    8
#define PHN      24
#define PWN      24
#define PATCHES  576
#define DIM      1024
#define NRL      12
#define NPAIRS   28
#define OUTH     336
#define OUTW     336
#define PADP     640
#define TILEM    192
#define KS       64             // k per slab (128 B fp16, SW128)
#define NSLAB    16
#define NTHR     128            // 4 warps, warp tile 96x96
#define MATB     (TILEM * 128)  // 24576
#define STAGEB   (2 * MATB)     // 49152
#define TXB      STAGEB
#define SMEM_DYN (2048 + 2 * STAGEB)   // 100352 -> 2 CTAs/SM

// ---------------- device scratch ----------------
__device__ __align__(128) __half g_featn[(size_t)NRL * BATCH * PADP * DIM];
__device__ unsigned g_keys[NRL * BATCH * PADP * BATCH];
__device__ float    g_scores[BATCH * PATCHES];
__device__ unsigned g_img[BATCH];

__device__ __forceinline__ unsigned enc_f(float x) {
    unsigned u = __float_as_uint(x);
    return (u & 0x80000000u) ? ~u : (u | 0x80000000u);
}
__device__ __forceinline__ float dec_f(unsigned k) {
    unsigned u = (k & 0x80000000u) ? (k & 0x7FFFFFFFu) : ~k;
    return __uint_as_float(u);
}
__device__ __forceinline__ uint32_t smem_u32(const void* p) {
    uint32_t a;
    asm("{ .reg .u64 t; cvta.to.shared.u64 t, %1; cvt.u32.u64 %0, t; }" : "=r"(a) : "l"(p));
    return a;
}

#define MBAR_INIT(a, n) asm volatile("mbarrier.init.shared.b64 [%0], %1;" :: "r"(a), "r"(n) : "memory")
#define MBAR_EXPECT(a, tx) asm volatile("mbarrier.arrive.expect_tx.shared.b64 _, [%0], %1;" :: "r"(a), "r"(tx) : "memory")
#define MBAR_WAIT(a, ph) do { \
    uint32_t _m = (a), _p = (ph), _d; \
    asm volatile("{ .reg .pred p; mbarrier.try_wait.parity.acquire.cta.shared::cta.b64 p, [%1], %2; selp.b32 %0,1,0,p; }" \
        : "=r"(_d) : "r"(_m), "r"(_p) : "memory"); \
    if (!_d) { asm volatile("{ .reg .pred P1; WL_%=: mbarrier.try_wait.parity.acquire.cta.shared::cta.b64 P1, [%0], %1, 0x989680; @P1 bra.uni WD_%=; bra.uni WL_%=; WD_%=: }" \
        :: "r"(_m), "r"(_p) : "memory"); } \
} while (0)

#define TMA_LOAD_2D(dst, map, cx, cy, mbar) \
    asm volatile("cp.async.bulk.tensor.2d.shared::cta.global.tile.mbarrier::complete_tx::bytes " \
        "[%0], [%1, {%2, %3}], [%4];" \
        :: "r"(dst), "l"(map), "r"(cx), "r"(cy), "r"(mbar) : "memory")

#define LDSM_X4(r0, r1, r2, r3, a) \
    asm volatile("ldmatrix.sync.aligned.m8n8.x4.shared.b16 {%0,%1,%2,%3}, [%4];" \
        : "=r"(r0), "=r"(r1), "=r"(r2), "=r"(r3) : "r"(a))

#define MMA16816H(c, a, b) \
    asm volatile("mma.sync.aligned.m16n8k16.row.col.f16.f16.f16.f16 " \
        "{%0,%1}, {%2,%3,%4,%5}, {%6,%7}, {%0,%1};" \
        : "+r"((c)[0]), "+r"((c)[1]) \
        : "r"((a)[0]), "r"((a)[1]), "r"((a)[2]), "r"((a)[3]), "r"((b)[0]), "r"((b)[1]))

// ---------------- pool + normalize -> fp16 (4 patches/block) ----------------
__global__ void __launch_bounds__(256) pool_norm_kernel(const float* __restrict__ feat) {
    int bx = blockIdx.x, b = blockIdx.y, l = blockIdx.z;
    int ph = bx / 6, pwg = bx % 6;
    int pw0 = pwg * 4;
    int t = threadIdx.x;
    int d0 = t * 4;

    {
        int lin = (l * BATCH + b) * 144 + bx;
        if (lin < (NRL * BATCH * PADP * BATCH) / 256)
            g_keys[lin * 256 + t] = 0u;
        if (lin == 0 && t < BATCH) g_img[t] = 0u;
    }

    const float* base = feat + ((size_t)(l * BATCH + b) * PATCHES) * DIM;

    float4 s1[4], s3[4], s5[4];
    #pragma unroll
    for (int j = 0; j < 4; ++j) {
        s1[j] = make_float4(0.f, 0.f, 0.f, 0.f);
        s3[j] = make_float4(0.f, 0.f, 0.f, 0.f);
        s5[j] = make_float4(0.f, 0.f, 0.f, 0.f);
    }

    #pragma unroll
    for (int dy = -2; dy <= 2; ++dy) {
        int y = ph + dy;
        if ((unsigned)y >= (unsigned)PHN) continue;
        bool in3y = (dy >= -1 && dy <= 1);
        bool in1y = (dy == 0);
        #pragma unroll
        for (int xi = 0; xi < 8; ++xi) {
            int x = pw0 - 2 + xi;
            if ((unsigned)x >= (unsigned)PWN) continue;
            const float4 v = *(const float4*)(base + (size_t)(y * PWN + x) * DIM + d0);
            #pragma unroll
            for (int j = 0; j < 4; ++j) {
                int dxi = xi - (j + 2);
                if (dxi >= -2 && dxi <= 2) {
                    s5[j].x += v.x; s5[j].y += v.y; s5[j].z += v.z; s5[j].w += v.w;
                    if (in3y && dxi >= -1 && dxi <= 1) {
                        s3[j].x += v.x; s3[j].y += v.y; s3[j].z += v.z; s3[j].w += v.w;
                        if (in1y && dxi == 0) s1[j] = v;
                    }
                }
            }
        }
    }
    #pragma unroll
    for (int j = 0; j < 4; ++j) {
        s3[j].x *= (1.f/9.f);  s3[j].y *= (1.f/9.f);  s3[j].z *= (1.f/9.f);  s3[j].w *= (1.f/9.f);
        s5[j].x *= (1.f/25.f); s5[j].y *= (1.f/25.f); s5[j].z *= (1.f/25.f); s5[j].w *= (1.f/25.f);
    }

    float q[12];
    #pragma unroll
    for (int j = 0; j < 4; ++j) {
        q[0 + j] = s1[j].x*s1[j].x + s1[j].y*s1[j].y + s1[j].z*s1[j].z + s1[j].w*s1[j].w;
        q[4 + j] = s3[j].x*s3[j].x + s3[j].y*s3[j].y + s3[j].z*s3[j].z + s3[j].w*s3[j].w;
        q[8 + j] = s5[j].x*s5[j].x + s5[j].y*s5[j].y + s5[j].z*s5[j].z + s5[j].w*s5[j].w;
    }
    #pragma unroll
    for (int k = 0; k < 12; ++k)
        #pragma unroll
        for (int o = 16; o > 0; o >>= 1)
            q[k] += __shfl_xor_sync(0xffffffffu, q[k], o);

    __shared__ float ws[8][12];
    __shared__ float rn[12];
    if ((t & 31) == 0)
        #pragma unroll
        for (int k = 0; k < 12; ++k) ws[t >> 5][k] = q[k];
    __syncthreads();
    if (t < 12) {
        float x = 0.f;
        #pragma unroll
        for (int w = 0; w < 8; ++w) x += ws[w][t];
        rn[t] = rsqrtf(x);
    }
    __syncthreads();

    #pragma unroll
    for (int ri = 0; ri < 3; ++ri) {
        int z = ri * 4 + l;
        #pragma unroll
        for (int j = 0; j < 4; ++j) {
            float4 v = (ri == 0) ? s1[j] : (ri == 1) ? s3[j] : s5[j];
            float r = rn[ri * 4 + j];
            __half2 lo = __floats2half2_rn(v.x * r, v.y * r);
            __half2 hi = __floats2half2_rn(v.z * r, v.w * r);
            uint2 pk = make_uint2(*(unsigned*)&lo, *(unsigned*)&hi);
            int p = ph * PWN + pw0 + j;
            *(uint2*)(g_featn + ((size_t)(z * BATCH + b) * PADP + p) * DIM + d0) = pk;
        }
    }
}

// ---------------- TMA + fp16 mma fused GEMM + bidirectional max --------------
// CTA tile 192x192, 4 warps (2x2) of 96x96, KS=64 (SW128), 2-stage smem,
// A-fragments register-double-buffered, 2 CTAs/SM.
__global__ void __launch_bounds__(NTHR, 2) gemm_max_mma(const __grid_constant__ CUtensorMap tmap) {
    extern __shared__ __align__(16) char dsm[];
    uint32_t sraw = smem_u32(dsm);
    uint32_t ub   = (sraw + 1023) & ~1023u;
    uint32_t sstg = ub + 1024;

    int t = threadIdx.x;
    int wid = t >> 5, lane = t & 31;
    int warp_m = wid & 1;
    int warp_n = wid >> 1;

    int tile = blockIdx.x;
    int ti = tile / 3, tj = tile % 3;
    int pair = blockIdx.y, rl = blockIdx.z;

    int b = 0, rem = pair;
    #pragma unroll
    for (int bb = 0; bb < 7; ++bb) {
        int cnt = 7 - bb;
        if (rem < cnt) { b = bb; break; }
        rem -= cnt;
    }
    int c = b + 1 + rem;

    int rowA = (rl * BATCH + b) * PADP + ti * TILEM;
    int rowB = (rl * BATCH + c) * PADP + tj * TILEM;

    if (t == 0) {
        MBAR_INIT(ub, 1); MBAR_INIT(ub + 8, 1);
        asm volatile("fence.proxy.async.shared::cta;" ::: "memory");
    }
    __syncthreads();
    if (t == 0) {
        #pragma unroll
        for (int s = 0; s < 2; ++s) {
            MBAR_EXPECT(ub + s * 8, TXB);
            TMA_LOAD_2D(sstg + s * STAGEB,        &tmap, s * 128, rowA, ub + s * 8);
            TMA_LOAD_2D(sstg + s * STAGEB + MATB, &tmap, s * 128, rowB, ub + s * 8);
        }
    }

    uint32_t acc[6][12][2];
    #pragma unroll
    for (int mi = 0; mi < 6; ++mi)
        #pragma unroll
        for (int ni = 0; ni < 12; ++ni) { acc[mi][ni][0] = 0u; acc[mi][ni][1] = 0u; }

    // SW128 swizzle in a 128B-wide box: byte col c at row r -> c ^ ((r&7)<<4)
    int rA = warp_m * 96 + (lane & 15);
    uint32_t xorA = (uint32_t)((rA & 7) << 4);
    uint32_t abase = (uint32_t)(rA * 128);
    uint32_t koA[4];
    #pragma unroll
    for (int ks = 0; ks < 4; ++ks)
        koA[ks] = (uint32_t)((ks * 32 + (lane >> 4) * 16)) ^ xorA;

    int rB = warp_n * 96 + (lane >> 4) * 8 + (lane & 7);
    uint32_t xorB = (uint32_t)((rB & 7) << 4);
    uint32_t bbase = (uint32_t)(MATB + rB * 128);
    uint32_t koB[4];
    #pragma unroll
    for (int ks = 0; ks < 4; ++ks)
        koB[ks] = (uint32_t)((ks * 32 + ((lane >> 3) & 1) * 16)) ^ xorB;

    uint32_t afr[2][6][4];   // A fragments, double-buffered

    for (int kc = 0; kc < NSLAB; ++kc) {
        int st = kc & 1;
        MBAR_WAIT(ub + st * 8, (kc >> 1) & 1);

        uint32_t Sb = sstg + st * STAGEB;

        // slab prologue: A fragments for ks=0 into buffer 0
        #pragma unroll
        for (int mi = 0; mi < 6; ++mi)
            LDSM_X4(afr[0][mi][0], afr[0][mi][1], afr[0][mi][2], afr[0][mi][3],
                    Sb + abase + mi * 2048 + koA[0]);

        #pragma unroll
        for (int ks = 0; ks < 4; ++ks) {
            int cur = ks & 1, nxt = cur ^ 1;
            // issue A loads for ks+1 before consuming current fragments
            if (ks < 3) {
                #pragma unroll
                for (int mi = 0; mi < 6; ++mi)
                    LDSM_X4(afr[nxt][mi][0], afr[nxt][mi][1], afr[nxt][mi][2], afr[nxt][mi][3],
                            Sb + abase + mi * 2048 + koA[ks + 1]);
            }
            // B fragments for ks (12 fragments = 6 LDSM.x4)
            uint32_t bfr[12][2];
            #pragma unroll
            for (int np = 0; np < 6; ++np)
                LDSM_X4(bfr[np * 2][0], bfr[np * 2][1], bfr[np * 2 + 1][0], bfr[np * 2 + 1][1],
                        Sb + bbase + np * 2048 + koB[ks]);
            #pragma unroll
            for (int mi = 0; mi < 6; ++mi)
                #pragma unroll
                for (int ni = 0; ni < 12; ++ni)
                    MMA16816H(acc[mi][ni], afr[cur][mi], bfr[ni]);
        }

        __syncthreads();   // all warps finished reading stage st
        if (t == 0 && kc + 2 < NSLAB) {
            MBAR_EXPECT(ub + st * 8, TXB);
            TMA_LOAD_2D(Sb,        &tmap, (kc + 2) * 128, rowA, ub + st * 8);
            TMA_LOAD_2D(Sb + MATB, &tmap, (kc + 2) * 128, rowB, ub + st * 8);
        }
    }

    // ---------------- epilogue: bidirectional max ----------------
    float* rowsmem = (float*)(dsm + (sstg - sraw));          // [2][192] by warp_n
    float* colsmem = rowsmem + 2 * 192;                      // [2][192] by warp_m

    #pragma unroll
    for (int mi = 0; mi < 6; ++mi) {
        __half2 h0 = __float2half2_rn(-60000.f), h1 = h0;
        #pragma unroll
        for (int ni = 0; ni < 12; ++ni) {
            h0 = __hmax2(h0, *(__half2*)&acc[mi][ni][0]);
            h1 = __hmax2(h1, *(__half2*)&acc[mi][ni][1]);
        }
        float rm0 = fmaxf(__low2float(h0), __high2float(h0));
        float rm1 = fmaxf(__low2float(h1), __high2float(h1));
        #pragma unroll
        for (int o = 1; o < 4; o <<= 1) {
            rm0 = fmaxf(rm0, __shfl_xor_sync(0xffffffffu, rm0, o));
            rm1 = fmaxf(rm1, __shfl_xor_sync(0xffffffffu, rm1, o));
        }
        if ((lane & 3) == 0) {
            int lr = warp_m * 96 + mi * 16 + (lane >> 2);
            rowsmem[warp_n * 192 + lr]     = rm0;
            rowsmem[warp_n * 192 + lr + 8] = rm1;
        }
    }

    #pragma unroll
    for (int ni = 0; ni < 12; ++ni) {
        __half2 hm = __float2half2_rn(-60000.f);
        #pragma unroll
        for (int mi = 0; mi < 6; ++mi) {
            hm = __hmax2(hm, *(__half2*)&acc[mi][ni][0]);
            hm = __hmax2(hm, *(__half2*)&acc[mi][ni][1]);
        }
        float cm0 = __low2float(hm);
        float cm1 = __high2float(hm);
        #pragma unroll
        for (int o = 4; o < 32; o <<= 1) {
            cm0 = fmaxf(cm0, __shfl_xor_sync(0xffffffffu, cm0, o));
            cm1 = fmaxf(cm1, __shfl_xor_sync(0xffffffffu, cm1, o));
        }
        if (lane < 4) {
            int lc = warp_n * 96 + ni * 8 + lane * 2;
            colsmem[warp_m * 192 + lc]     = cm0;
            colsmem[warp_m * 192 + lc + 1] = cm1;
        }
    }
    __syncthreads();

    for (int idx = t; idx < 192; idx += NTHR) {
        float mr = fmaxf(rowsmem[idx], rowsmem[192 + idx]);
        int p = ti * TILEM + idx;
        atomicMax(&g_keys[((size_t)(rl * BATCH + b) * PADP + p) * BATCH + c], enc_f(mr));
        float mc = fmaxf(colsmem[idx], colsmem[192 + idx]);
        int q = tj * TILEM + idx;
        atomicMax(&g_keys[((size_t)(rl * BATCH + c) * PADP + q) * BATCH + b], enc_f(mc));
    }
}

// ---------------- score (+ fused image max), rl-parallel ----------------
__global__ void score_kernel() {
    int t = threadIdx.x;
    int idx = blockIdx.x * 32 + (t >> 2);
    int rlg = t & 3;
    if (idx >= BATCH * PATCHES) return;
    int b = idx / PATCHES;
    int p = idx % PATCHES;

    float sum = 0.f;
    #pragma unroll
    for (int r = 0; r < 3; ++r) {
        int rl = rlg * 3 + r;
        const uint4* k4 = (const uint4*)&g_keys[((size_t)(rl * BATCH + b) * PADP + p) * BATCH];
        uint4 v0 = k4[0], v1 = k4[1];
        unsigned kv[8] = { v0.x, v0.y, v0.z, v0.w, v1.x, v1.y, v1.z, v1.w };
        float d1 = 1e30f, d2 = 1e30f;
        #pragma unroll
        for (int cc = 0; cc < BATCH; ++cc) {
            if (cc == b) continue;
            float dot = dec_f(kv[cc]);
            float d = sqrtf(fmaxf(2.0f - 2.0f * dot, 0.0f));
            if (d < d1) { d2 = d1; d1 = d; }
            else if (d < d2) { d2 = d; }
        }
        sum += 0.5f * (d1 + d2);
    }
    sum += __shfl_xor_sync(0xffffffffu, sum, 1);
    sum += __shfl_xor_sync(0xffffffffu, sum, 2);
    if (rlg == 0) {
        float s = sum * (1.0f / 12.0f);
        g_scores[idx] = s;
        atomicMax(&g_img[b], enc_f(s));
    }
}

__global__ void bilinear_kernel(float* __restrict__ out) {
    int idx = blockIdx.x * 256 + threadIdx.x;
    if (idx >= BATCH * OUTH * OUTW) return;
    if (idx < BATCH) out[idx] = dec_f(g_img[idx]);   // scores_image

    int b = idx / (OUTH * OUTW);
    int rr = idx % (OUTH * OUTW);
    int y = rr / OUTW, x = rr % OUTW;

    const float sc = 23.0f / 335.0f;
    float fy = (float)y * sc;
    float fx = (float)x * sc;
    int y0 = (int)floorf(fy); int y1 = min(y0 + 1, PHN - 1);
    int x0 = (int)floorf(fx); int x1 = min(x0 + 1, PWN - 1);
    float wy = fy - (float)y0;
    float wx = fx - (float)x0;

    const float* s = g_scores + b * PATCHES;
    float f00 = s[y0 * PWN + x0];
    float f01 = s[y0 * PWN + x1];
    float f10 = s[y1 * PWN + x0];
    float f11 = s[y1 * PWN + x1];

    out[BATCH + idx] = f00 * (1.f - wy) * (1.f - wx) + f01 * (1.f - wy) * wx
                     + f10 * wy * (1.f - wx)         + f11 * wy * wx;
}

// ---------------- launch ----------------
typedef CUresult (*PFN_TMapEncode)(
    CUtensorMap*, CUtensorMapDataType, cuuint32_t, void*,
    const cuuint64_t*, const cuuint64_t*, const cuuint32_t*, const cuuint32_t*,
    CUtensorMapInterleave, CUtensorMapSwizzle, CUtensorMapL2promotion,
    CUtensorMapFloatOOBfill);

extern "C" void kernel_launch(void* const* d_in, const int* in_sizes, int n_in,
                              void* d_out, int out_size) {
    const float* feat = (const float*)d_in[0];
    float* out = (float*)d_out;

    static CUtensorMap tmap;
    {
        void* fn = nullptr;
        cudaDriverEntryPointQueryResult qres;
        cudaGetDriverEntryPointByVersion("cuTensorMapEncodeTiled", &fn, 12000,
                                         cudaEnableDefault, &qres);
        void* gptr = nullptr;
        cudaGetSymbolAddress(&gptr, g_featn);
        cuuint64_t dims[2]    = { (cuuint64_t)(DIM * 2), (cuuint64_t)(NRL * BATCH * PADP) };
        cuuint64_t strides[1] = { (cuuint64_t)(DIM * 2) };
        cuuint32_t box[2]     = { 128u, (cuuint32_t)TILEM };
        cuuint32_t estr[2]    = { 1u, 1u };
        if (fn) {
            ((PFN_TMapEncode)fn)(&tmap, CU_TENSOR_MAP_DATA_TYPE_UINT8, 2, gptr,
                                 dims, strides, box, estr,
                                 CU_TENSOR_MAP_INTERLEAVE_NONE,
                                 CU_TENSOR_MAP_SWIZZLE_128B,
                                 CU_TENSOR_MAP_L2_PROMOTION_L2_128B,
                                 CU_TENSOR_MAP_FLOAT_OOB_FILL_NONE);
        }
    }

    cudaFuncSetAttribute(gemm_max_mma, cudaFuncAttributeMaxDynamicSharedMemorySize, SMEM_DYN);

    pool_norm_kernel<<<dim3(144, BATCH, L_LAYERS), 256>>>(feat);
    gemm_max_mma<<<dim3(9, NPAIRS, NRL), NTHR, SMEM_DYN>>>(tmap);
    score_kernel<<<144, 128>>>();
    bilinear_kernel<<<(BATCH * OUTH * OUTW + 255) / 256, 256>>>(out);
}